// round 4
// baseline (speedup 1.0000x reference)
#include <cuda_runtime.h>
#include <math.h>

// Fixed shapes for EpisodicMemory_57810259804539
#define BB 4
#define HH 16
#define SS 2048
#define DD 64
#define MM 1000
#define KK 10
#define HID (HH*DD)       // 1024
#define TT (SS+KK)        // 2058
#define EPSV 1e-8f

#define N0_4  ((long long)BB*SS*HID/4)         // 2,097,152  inputs as float4
#define NQ_4  N0_4                              // q as float4
#define NB_4  ((long long)BB*HH*SS*DD/4)        // k/v body as float4
#define NK_4  ((long long)BB*HH*TT*DD/4)        // 2,107,392  k_aug/v_aug as float4
#define HID4  (HID/4)                           // 256 float4 per memory row

#define CHUNK4 1024                              // float4 per copy block
#define COPY_BLOCKS ((int)((N0_4 + NQ_4 + 2*NB_4) / CHUNK4))   // 8192

// ---------------------------------------------------------------------------
// ONE kernel.
//   blocks 0..3 : batch b — sims (self-contained), top-10, gather, mask, pos
//   blocks 4..  : bulk float4 copies, 4 float4 per thread (ILP-4)
// ---------------------------------------------------------------------------
__global__ void __launch_bounds__(256) fused_kernel(
    const float4* __restrict__ inputs4,
    const float4* __restrict__ q4,
    const float4* __restrict__ k4,
    const float4* __restrict__ v4,
    const float4* __restrict__ mk4,
    const float4* __restrict__ mv4,
    const float*  __restrict__ attn_mask,
    const float*  __restrict__ mem_pos,
    float4* __restrict__ out4,
    float*  __restrict__ out,
    long long off_mask, long long off_pos,
    long long off_seq, int has_scalar)
{
    const long long OFFK4 = N0_4 + NQ_4;            // k_aug start (float4)
    const long long OFFV4 = OFFK4 + NK_4;           // v_aug start

    if (blockIdx.x >= BB) {
        // ---------------- bulk copy blocks (ILP-4, 16KB/block) -----------
        long long base = (long long)(blockIdx.x - BB) * CHUNK4 + threadIdx.x;
        const float4* src;
        long long dst0;

        if (base < N0_4) {
            src = inputs4; dst0 = base;
        } else if (base < N0_4 + NQ_4) {
            long long e = base - N0_4;
            src = q4 + e - base;     // src[base] == q4[e]
            dst0 = N0_4 + e - base + base;  // == N0_4 + e
            src = q4 - N0_4;                // so src[base] = q4[base - N0_4]
            dst0 = base;                    // out4[base] (regions contiguous)
        } else if (base < N0_4 + NQ_4 + NB_4) {
            long long e = base - (N0_4 + NQ_4);
            // all 1024 elems of this block share bh (chunks don't cross bh)
            long long bh = e >> 15;          // e / (2048*16)
            src  = k4 - (N0_4 + NQ_4);       // src[base] = k4[e]
            dst0 = OFFK4 - (N0_4 + NQ_4) + 160*(bh + 1) + base; // dst for this e
            dst0 -= base; dst0 += base;      // keep as absolute lambda below
            dst0 = OFFK4 + e + 160*(bh + 1);
            dst0 -= e;  // dst = dst0 + e_j where e_j = base_j - (N0_4+NQ_4)
            dst0 += base - (N0_4 + NQ_4);
            dst0 -= (base - (N0_4 + NQ_4));
            dst0 = OFFK4 + 160*(bh + 1) - (N0_4 + NQ_4);  // add base_j later
        } else {
            long long e = base - (N0_4 + NQ_4 + NB_4);
            long long bh = e >> 15;
            src  = v4 - (N0_4 + NQ_4 + NB_4);
            dst0 = OFFV4 + 160*(bh + 1) - (N0_4 + NQ_4 + NB_4);
        }

        // dst for element index i: region 0/1 -> i ; region 2/3 -> dst0 + i
        bool shifted = (base >= N0_4 + NQ_4);
        long long i0 = base, i1 = base + 256, i2 = base + 512, i3 = base + 768;
        float4 a0 = src[i0];
        float4 a1 = src[i1];
        float4 a2 = src[i2];
        float4 a3 = src[i3];
        if (shifted) {
            out4[dst0 + i0] = a0;
            out4[dst0 + i1] = a1;
            out4[dst0 + i2] = a2;
            out4[dst0 + i3] = a3;
        } else {
            out4[i0] = a0;
            out4[i1] = a1;
            out4[i2] = a2;
            out4[i3] = a3;
        }
        return;
    }

    // ---------------- retrieval block for batch b ------------------------
    int b = blockIdx.x;
    int tid = threadIdx.x;
    int wid = tid >> 5, lane = tid & 31;

    __shared__ float4 qk4s[HID4];     // query key, [h*16+d4]
    __shared__ float  ss[MM];
    __shared__ float  rv[256];
    __shared__ int    ri[256];
    __shared__ int    top[KK];

    // query_key[b] = k[b, :, S-1, :]
    {
        int h = tid >> 4, d4 = tid & 15;
        qk4s[tid] = k4[(((long long)b*HH + h)*SS + (SS-1))*16 + d4];
    }
    __syncthreads();

    // sims: warp w handles rows m = w, w+8, ...
    for (int m = wid; m < MM; m += 8) {
        const float4* row = mk4 + (size_t)m * HID4;
        float dot = 0.f, sq = 0.f;
        #pragma unroll
        for (int j = 0; j < 8; j++) {
            int i4 = lane + 32*j;
            float4 r = row[i4];
            float4 qv = qk4s[i4];
            dot += qv.x*r.x + qv.y*r.y + qv.z*r.z + qv.w*r.w;
            sq  += r.x*r.x + r.y*r.y + r.z*r.z + r.w*r.w;
        }
        #pragma unroll
        for (int off = 16; off; off >>= 1) {
            dot += __shfl_down_sync(0xffffffffu, dot, off);
            sq  += __shfl_down_sync(0xffffffffu, sq,  off);
        }
        if (lane == 0)
            ss[m] = dot / (sqrtf(sq) + EPSV);
    }
    __syncthreads();

    // top-10: descending, lowest index on ties
    for (int j = 0; j < KK; j++) {
        float bv = -INFINITY; int bi = MM;
        for (int m = tid; m < MM; m += 256) {
            float vv = ss[m];
            if (vv > bv) { bv = vv; bi = m; }
        }
        rv[tid] = bv; ri[tid] = bi;
        __syncthreads();
        for (int off = 128; off; off >>= 1) {
            if (tid < off) {
                float ov = rv[tid + off]; int oi = ri[tid + off];
                if (ov > rv[tid] || (ov == rv[tid] && oi < ri[tid])) {
                    rv[tid] = ov; ri[tid] = oi;
                }
            }
            __syncthreads();
        }
        if (tid == 0) { top[j] = ri[0]; ss[ri[0]] = -INFINITY; }
        __syncthreads();
    }

    // gather retrieved rows t<K of k_aug / v_aug
    for (int e = tid; e < 2*KK*HID4; e += 256) {
        int which = e >= KK*HID4;
        int e2 = which ? e - KK*HID4 : e;
        int t  = e2 >> 8;
        int i4 = e2 & 255;
        int idx = top[t];
        float4 val = (which ? mv4 : mk4)[(size_t)idx*HID4 + i4];
        long long dst = (which ? OFFV4 : OFFK4)
                      + (((long long)b*HH + (i4 >> 4))*TT + t)*16 + (i4 & 15);
        out4[dst] = val;
    }

    // mask_aug[b] = [ones(K), attention_mask[b]]
    for (int t = tid; t < TT; t += 256)
        out[off_mask + (size_t)b*TT + t] =
            (t < KK) ? 1.0f : attn_mask[(size_t)b*SS + (t - KK)];

    // positions_k[b] = [arange(S), mem_positions[top_idx[b]]]
    for (int t = tid; t < TT; t += 256)
        out[off_pos + (size_t)b*TT + t] =
            (t < SS) ? (float)t : mem_pos[top[t - SS]];

    if (b == 0 && tid == 0 && has_scalar)
        out[off_seq] = (float)TT;
}

// ---------------------------------------------------------------------------
extern "C" void kernel_launch(void* const* d_in, const int* in_sizes, int n_in,
                              void* d_out, int out_size)
{
    const float* inputs = (const float*)d_in[0];
    const float* q      = (const float*)d_in[1];
    const float* k      = (const float*)d_in[2];
    const float* v      = (const float*)d_in[3];
    const float* mask   = (const float*)d_in[4];
    const float* mk     = (const float*)d_in[5];
    const float* mv     = (const float*)d_in[6];
    const float* mpos   = (const float*)d_in[7];
    float* out = (float*)d_out;

    const long long N0 = 4 * N0_4;
    const long long NQ = 4 * NQ_4;
    const long long NK = 4 * NK_4;

    const long long off_mask = N0 + NQ + 2*NK;
    const long long off_tail = off_mask + (long long)BB * TT;
    // tuple order: inputs, q, k_aug, v_aug, mask_aug, seq_len_k, positions_k
    const long long with_scalar = off_tail + 1 + (long long)BB * TT;
    int has_scalar = ((long long)out_size == with_scalar) ? 1 : 0;
    const long long off_seq = off_tail;
    const long long off_pos = off_tail + (has_scalar ? 1 : 0);

    fused_kernel<<<BB + COPY_BLOCKS, 256>>>(
        (const float4*)inputs, (const float4*)q,
        (const float4*)k, (const float4*)v,
        (const float4*)mk, (const float4*)mv,
        mask, mpos,
        (float4*)out, out,
        off_mask, off_pos, off_seq, has_scalar);
}

// round 5
// speedup vs baseline: 4.5643x; 4.5643x over previous
#include <cuda_runtime.h>
#include <math.h>

// Fixed shapes for EpisodicMemory_57810259804539
#define BB 4
#define HH 16
#define SS 2048
#define DD 64
#define MM 1000
#define KK 10
#define HID (HH*DD)       // 1024
#define TT (SS+KK)        // 2058
#define EPSV 1e-8f

#define N0_4  ((long long)BB*SS*HID/4)         // 2,097,152  inputs as float4
#define NQ_4  N0_4                              // q as float4
#define NB_4  ((long long)BB*HH*SS*DD/4)        // k/v body as float4
#define NK_4  ((long long)BB*HH*TT*DD/4)        // 2,107,392  k_aug/v_aug as float4
#define HID4  (HID/4)                           // 256 float4 per memory row

#define NTHR   1024
#define CHUNK4 4096                              // float4 per copy block (4/thread)
#define COPY_BLOCKS ((int)((N0_4 + NQ_4 + 2*NB_4) / CHUNK4))   // 2048

// ---------------------------------------------------------------------------
// ONE kernel, 1024 threads/block.
//   blocks 0..3 : batch b — sims (32 warps), top-10, gather, mask, pos.
//                 Start in wave 1, finish hidden under the copy wave.
//   blocks 4..  : bulk float4 copies, ILP-4.
// ---------------------------------------------------------------------------
__global__ void __launch_bounds__(NTHR) fused_kernel(
    const float4* __restrict__ inputs4,
    const float4* __restrict__ q4,
    const float4* __restrict__ k4,
    const float4* __restrict__ v4,
    const float4* __restrict__ mk4,
    const float4* __restrict__ mv4,
    const float*  __restrict__ attn_mask,
    const float*  __restrict__ mem_pos,
    float4* __restrict__ out4,
    float*  __restrict__ out,
    long long off_mask, long long off_pos,
    long long off_seq, int has_scalar)
{
    const long long OFFK4 = N0_4 + NQ_4;            // k_aug start (float4)
    const long long OFFV4 = OFFK4 + NK_4;           // v_aug start

    if (blockIdx.x >= BB) {
        // ---------------- bulk copy blocks (64KB/block, ILP-4) -----------
        long long base = (long long)(blockIdx.x - BB) * CHUNK4 + threadIdx.x;
        // All 4 elements (base, +1024, +2048, +3072) stay inside one region
        // and one bh row-group (regions and bh-groups are 4096-multiples).
        if (base < N0_4 + NQ_4) {
            const float4* s = (base < N0_4) ? inputs4 : (q4 - N0_4);
            float4 a0 = s[base];
            float4 a1 = s[base + 1024];
            float4 a2 = s[base + 2048];
            float4 a3 = s[base + 3072];
            out4[base]        = a0;
            out4[base + 1024] = a1;
            out4[base + 2048] = a2;
            out4[base + 3072] = a3;
        } else if (base < N0_4 + NQ_4 + NB_4) {
            long long e = base - (N0_4 + NQ_4);
            float4 a0 = k4[e];
            float4 a1 = k4[e + 1024];
            float4 a2 = k4[e + 2048];
            float4 a3 = k4[e + 3072];
            // dst = OFFK4 + (bh*TT + KK + t)*16 + d4  = OFFK4 + e + 160*(bh+1)
            long long dst = OFFK4 + e + 160*((e >> 15) + 1);
            out4[dst]        = a0;
            out4[dst + 1024] = a1;
            out4[dst + 2048] = a2;
            out4[dst + 3072] = a3;
        } else {
            long long e = base - (N0_4 + NQ_4 + NB_4);
            float4 a0 = v4[e];
            float4 a1 = v4[e + 1024];
            float4 a2 = v4[e + 2048];
            float4 a3 = v4[e + 3072];
            long long dst = OFFV4 + e + 160*((e >> 15) + 1);
            out4[dst]        = a0;
            out4[dst + 1024] = a1;
            out4[dst + 2048] = a2;
            out4[dst + 3072] = a3;
        }
        return;
    }

    // ---------------- retrieval block for batch b (32 warps) -------------
    int b = blockIdx.x;
    int tid = threadIdx.x;
    int wid = tid >> 5, lane = tid & 31;

    __shared__ float4 qk4s[HID4];     // query key [h*16+d4], 4KB
    __shared__ float  ss[MM];
    __shared__ float  rv[NTHR];
    __shared__ int    ri[NTHR];
    __shared__ int    top[KK];

    // query_key[b] = k[b, :, S-1, :]
    if (tid < HID4) {
        int h = tid >> 4, d4 = tid & 15;
        qk4s[tid] = k4[(((long long)b*HH + h)*SS + (SS-1))*16 + d4];
    }
    __syncthreads();

    // sims: warp w handles rows m = w, w+32, ...  (<= 32 rows/warp)
    for (int m = wid; m < MM; m += 32) {
        const float4* row = mk4 + (size_t)m * HID4;
        float dot = 0.f, sq = 0.f;
        #pragma unroll
        for (int j = 0; j < 8; j++) {
            int i4 = lane + 32*j;
            float4 r = row[i4];
            float4 qv = qk4s[i4];
            dot += qv.x*r.x + qv.y*r.y + qv.z*r.z + qv.w*r.w;
            sq  += r.x*r.x + r.y*r.y + r.z*r.z + r.w*r.w;
        }
        #pragma unroll
        for (int off = 16; off; off >>= 1) {
            dot += __shfl_down_sync(0xffffffffu, dot, off);
            sq  += __shfl_down_sync(0xffffffffu, sq,  off);
        }
        if (lane == 0)
            ss[m] = dot / (sqrtf(sq) + EPSV);
    }
    __syncthreads();

    // top-10: descending, lowest index on ties. MM < NTHR: 1 elem/thread.
    for (int j = 0; j < KK; j++) {
        float bv = (tid < MM) ? ss[tid] : -INFINITY;
        int   bi = (tid < MM) ? tid     : MM;
        rv[tid] = bv; ri[tid] = bi;
        __syncthreads();
        for (int off = 512; off; off >>= 1) {
            if (tid < off) {
                float ov = rv[tid + off]; int oi = ri[tid + off];
                if (ov > rv[tid] || (ov == rv[tid] && oi < ri[tid])) {
                    rv[tid] = ov; ri[tid] = oi;
                }
            }
            __syncthreads();
        }
        if (tid == 0) { top[j] = ri[0]; ss[ri[0]] = -INFINITY; }
        __syncthreads();
    }

    // gather retrieved rows t<K of k_aug / v_aug (5120 float4)
    for (int e = tid; e < 2*KK*HID4; e += NTHR) {
        int which = e >= KK*HID4;
        int e2 = which ? e - KK*HID4 : e;
        int t  = e2 >> 8;
        int i4 = e2 & 255;
        int idx = top[t];
        float4 val = (which ? mv4 : mk4)[(size_t)idx*HID4 + i4];
        long long dst = (which ? OFFV4 : OFFK4)
                      + (((long long)b*HH + (i4 >> 4))*TT + t)*16 + (i4 & 15);
        out4[dst] = val;
    }

    // mask_aug[b] = [ones(K), attention_mask[b]]
    for (int t = tid; t < TT; t += NTHR)
        out[off_mask + (size_t)b*TT + t] =
            (t < KK) ? 1.0f : attn_mask[(size_t)b*SS + (t - KK)];

    // positions_k[b] = [arange(S), mem_positions[top_idx[b]]]
    for (int t = tid; t < TT; t += NTHR)
        out[off_pos + (size_t)b*TT + t] =
            (t < SS) ? (float)t : mem_pos[top[t - SS]];

    if (b == 0 && tid == 0 && has_scalar)
        out[off_seq] = (float)TT;
}

// ---------------------------------------------------------------------------
extern "C" void kernel_launch(void* const* d_in, const int* in_sizes, int n_in,
                              void* d_out, int out_size)
{
    const float* inputs = (const float*)d_in[0];
    const float* q      = (const float*)d_in[1];
    const float* k      = (const float*)d_in[2];
    const float* v      = (const float*)d_in[3];
    const float* mask   = (const float*)d_in[4];
    const float* mk     = (const float*)d_in[5];
    const float* mv     = (const float*)d_in[6];
    const float* mpos   = (const float*)d_in[7];
    float* out = (float*)d_out;

    const long long N0 = 4 * N0_4;
    const long long NQ = 4 * NQ_4;
    const long long NK = 4 * NK_4;

    const long long off_mask = N0 + NQ + 2*NK;
    const long long off_tail = off_mask + (long long)BB * TT;
    // tuple order: inputs, q, k_aug, v_aug, mask_aug, seq_len_k, positions_k
    const long long with_scalar = off_tail + 1 + (long long)BB * TT;
    int has_scalar = ((long long)out_size == with_scalar) ? 1 : 0;
    const long long off_seq = off_tail;
    const long long off_pos = off_tail + (has_scalar ? 1 : 0);

    fused_kernel<<<BB + COPY_BLOCKS, NTHR>>>(
        (const float4*)inputs, (const float4*)q,
        (const float4*)k, (const float4*)v,
        (const float4*)mk, (const float4*)mv,
        mask, mpos,
        (float4*)out, out,
        off_mask, off_pos, off_seq, has_scalar);
}

// round 6
// speedup vs baseline: 8.6213x; 1.8888x over previous
#include <cuda_runtime.h>
#include <math.h>

// Fixed shapes for EpisodicMemory_57810259804539
#define BB 4
#define HH 16
#define SS 2048
#define DD 64
#define MM 1000
#define KK 10
#define HID (HH*DD)       // 1024
#define TT (SS+KK)        // 2058
#define EPSV 1e-8f

#define N0_4  ((long long)BB*SS*HID/4)         // 2,097,152  inputs as float4
#define NQ_4  N0_4                              // q as float4
#define NB_4  ((long long)BB*HH*SS*DD/4)        // k/v body as float4
#define NK_4  ((long long)BB*HH*TT*DD/4)        // 2,107,392  k_aug/v_aug as float4
#define HID4  (HID/4)                           // 256 float4 per memory row

#define SIMS_BLOCKS 500                          // 8 warps each -> 4000 (b,m)
#define RET_BLOCKS  BB
#define FIRST_SIMS  RET_BLOCKS                   // 4
#define FIRST_COPY  (RET_BLOCKS + SIMS_BLOCKS)   // 504
#define COPY_BLOCKS ((int)((N0_4 + NQ_4 + 2*NB_4) / 256))  // 32768

// Scratch + join state (zero-initialized at load; reset in-kernel per launch)
__device__ float g_sims[BB*MM];
__device__ unsigned int g_count;   // sims blocks arrived
__device__ unsigned int g_pass;    // retrieval blocks past snapshot

// ---------------------------------------------------------------------------
// ONE kernel, 256 threads/block.
//   blocks 0..3     : retrieval (spin-join on sims, top-10, gather, mask, pos)
//   blocks 4..503   : sims, one warp per (b,m)
//   blocks 504..    : bulk float4 copies (R2-proven config: 1 float4/thread)
// ---------------------------------------------------------------------------
__global__ void __launch_bounds__(256) fused_kernel(
    const float4* __restrict__ inputs4,
    const float4* __restrict__ q4,
    const float4* __restrict__ k4,
    const float4* __restrict__ v4,
    const float4* __restrict__ mk4,
    const float4* __restrict__ mv4,
    const float*  __restrict__ attn_mask,
    const float*  __restrict__ mem_pos,
    float4* __restrict__ out4,
    float*  __restrict__ out,
    long long off_mask, long long off_pos,
    long long off_seq, int has_scalar)
{
    const long long OFFK4 = N0_4 + NQ_4;            // k_aug start (float4)
    const long long OFFV4 = OFFK4 + NK_4;           // v_aug start
    int tid = threadIdx.x;

    if (blockIdx.x >= FIRST_COPY) {
        // ---------------- bulk copy blocks -------------------------------
        long long e = (long long)(blockIdx.x - FIRST_COPY) * 256 + tid;
        if (e < N0_4) { out4[e] = inputs4[e]; return; }
        e -= N0_4;
        if (e < NQ_4) { out4[N0_4 + e] = q4[e]; return; }
        e -= NQ_4;
        if (e < NB_4) {
            // dst = OFFK4 + (bh*TT + KK + t)*16 + d4 = OFFK4 + e + 160*(bh+1)
            out4[OFFK4 + e + 160*((e >> 15) + 1)] = k4[e];
            return;
        }
        e -= NB_4;
        out4[OFFV4 + e + 160*((e >> 15) + 1)] = v4[e];
        return;
    }

    if (blockIdx.x >= FIRST_SIMS) {
        // ---------------- sims blocks: one warp per (b,m) ----------------
        int wid = tid >> 5, lane = tid & 31;
        int wb = (blockIdx.x - FIRST_SIMS) * 8 + wid;     // 0..3999
        int b = wb / MM, m = wb % MM;

        const float4* row = mk4 + (size_t)m * HID4;
        // query_key[b][i] = k[b, i/64, S-1, i%64]; float4 chunks never cross h
        const float4* kb = k4 + (((long long)b*HH)*SS + (SS-1))*16;

        float dot = 0.f, sq = 0.f;
        #pragma unroll
        for (int j = 0; j < 8; j++) {
            int i4 = lane + 32*j;                 // 0..255
            float4 r  = row[i4];
            float4 qv = kb[(long long)(i4 >> 4)*SS*16 + (i4 & 15)];
            dot += qv.x*r.x + qv.y*r.y + qv.z*r.z + qv.w*r.w;
            sq  += r.x*r.x + r.y*r.y + r.z*r.z + r.w*r.w;
        }
        #pragma unroll
        for (int off = 16; off; off >>= 1) {
            dot += __shfl_down_sync(0xffffffffu, dot, off);
            sq  += __shfl_down_sync(0xffffffffu, sq,  off);
        }
        if (lane == 0)
            g_sims[wb] = dot / (sqrtf(sq) + EPSV);
        __syncthreads();
        if (tid == 0) {
            __threadfence();
            atomicAdd(&g_count, 1u);
        }
        return;
    }

    // ---------------- retrieval block for batch b ------------------------
    int b = blockIdx.x;
    __shared__ float ss[MM];
    __shared__ float rv[256];
    __shared__ int   ri[256];
    __shared__ int   top[KK];

    // join: wait for all 500 sims blocks
    if (tid == 0) {
        while (atomicAdd(&g_count, 0u) < (unsigned)SIMS_BLOCKS) { }
        __threadfence();
    }
    __syncthreads();

    // snapshot sims to smem, then signal we no longer need g_sims/g_count
    for (int i = tid; i < MM; i += 256)
        ss[i] = g_sims[b*MM + i];
    __syncthreads();
    if (tid == 0) atomicAdd(&g_pass, 1u);

    // top-10: descending, lowest index on ties
    for (int j = 0; j < KK; j++) {
        float bv = -INFINITY; int bi = MM;
        for (int m = tid; m < MM; m += 256) {
            float vv = ss[m];
            if (vv > bv) { bv = vv; bi = m; }   // strict > => lowest idx wins
        }
        rv[tid] = bv; ri[tid] = bi;
        __syncthreads();
        for (int off = 128; off; off >>= 1) {
            if (tid < off) {
                float ov = rv[tid + off]; int oi = ri[tid + off];
                if (ov > rv[tid] || (ov == rv[tid] && oi < ri[tid])) {
                    rv[tid] = ov; ri[tid] = oi;
                }
            }
            __syncthreads();
        }
        if (tid == 0) { top[j] = ri[0]; ss[ri[0]] = -INFINITY; }
        __syncthreads();
    }

    // gather retrieved rows t<K of k_aug / v_aug (5120 float4)
    for (int e = tid; e < 2*KK*HID4; e += 256) {
        int which = e >= KK*HID4;
        int e2 = which ? e - KK*HID4 : e;
        int t  = e2 >> 8;
        int i4 = e2 & 255;
        int idx = top[t];
        float4 val = (which ? mv4 : mk4)[(size_t)idx*HID4 + i4];
        long long dst = (which ? OFFV4 : OFFK4)
                      + (((long long)b*HH + (i4 >> 4))*TT + t)*16 + (i4 & 15);
        out4[dst] = val;
    }

    // mask_aug[b] = [ones(K), attention_mask[b]]
    for (int t = tid; t < TT; t += 256)
        out[off_mask + (size_t)b*TT + t] =
            (t < KK) ? 1.0f : attn_mask[(size_t)b*SS + (t - KK)];

    // positions_k[b] = [arange(S), mem_positions[top_idx[b]]]
    for (int t = tid; t < TT; t += 256)
        out[off_pos + (size_t)b*TT + t] =
            (t < SS) ? (float)t : mem_pos[top[t - SS]];

    if (b == 0 && tid == 0 && has_scalar)
        out[off_seq] = (float)TT;

    // block 0 resets join state for the next graph replay (after all 4
    // retrieval blocks have snapshotted sims)
    if (b == 0 && tid == 0) {
        while (atomicAdd(&g_pass, 0u) < (unsigned)RET_BLOCKS) { }
        g_count = 0u;
        g_pass  = 0u;
        __threadfence();
    }
}

// ---------------------------------------------------------------------------
extern "C" void kernel_launch(void* const* d_in, const int* in_sizes, int n_in,
                              void* d_out, int out_size)
{
    const float* inputs = (const float*)d_in[0];
    const float* q      = (const float*)d_in[1];
    const float* k      = (const float*)d_in[2];
    const float* v      = (const float*)d_in[3];
    const float* mask   = (const float*)d_in[4];
    const float* mk     = (const float*)d_in[5];
    const float* mv     = (const float*)d_in[6];
    const float* mpos   = (const float*)d_in[7];
    float* out = (float*)d_out;

    const long long N0 = 4 * N0_4;
    const long long NQ = 4 * NQ_4;
    const long long NK = 4 * NK_4;

    const long long off_mask = N0 + NQ + 2*NK;
    const long long off_tail = off_mask + (long long)BB * TT;
    // tuple order: inputs, q, k_aug, v_aug, mask_aug, seq_len_k, positions_k
    const long long with_scalar = off_tail + 1 + (long long)BB * TT;
    int has_scalar = ((long long)out_size == with_scalar) ? 1 : 0;
    const long long off_seq = off_tail;
    const long long off_pos = off_tail + (has_scalar ? 1 : 0);

    fused_kernel<<<FIRST_COPY + COPY_BLOCKS, 256>>>(
        (const float4*)inputs, (const float4*)q,
        (const float4*)k, (const float4*)v,
        (const float4*)mk, (const float4*)mv,
        mask, mpos,
        (float4*)out, out,
        off_mask, off_pos, off_seq, has_scalar);
}

// round 7
// speedup vs baseline: 8.9646x; 1.0398x over previous
#include <cuda_runtime.h>
#include <math.h>

// Fixed shapes for EpisodicMemory_57810259804539
#define BB 4
#define HH 16
#define SS 2048
#define DD 64
#define MM 1000
#define KK 10
#define HID (HH*DD)       // 1024
#define TT (SS+KK)        // 2058
#define EPSV 1e-8f

#define N0_4  ((long long)BB*SS*HID/4)         // 2,097,152  inputs as float4
#define NQ_4  N0_4                              // q as float4
#define NB_4  ((long long)BB*HH*SS*DD/4)        // k/v body as float4
#define NK_4  ((long long)BB*HH*TT*DD/4)        // 2,107,392  k_aug/v_aug as float4
#define HID4  (HID/4)                           // 256 float4 per memory row

#define CHUNK4     512                           // float4 per copy chunk (2/thread)
#define TOT_CHUNKS ((int)((N0_4 + NQ_4 + 2*NB_4) / CHUNK4))   // 16384
#define K1_CHUNKS  4096                          // ~25% of copy in kernel 1
#define K2_CHUNKS  (TOT_CHUNKS - K1_CHUNKS)      // 12288
#define SIMS_BLOCKS 500                          // 8 warps each -> 4000 (b,m)

// Scratch
__device__ float g_sims[BB*MM];

// ---------------------------------------------------------------------------
// Shared copy chunk: 512 float4, 2 per thread (stride 256). Regions and bh
// row-groups are multiples of 512, so a chunk never straddles either.
// ---------------------------------------------------------------------------
__device__ __forceinline__ void copy_chunk(
    long long c, int tid,
    const float4* __restrict__ inputs4, const float4* __restrict__ q4,
    const float4* __restrict__ k4, const float4* __restrict__ v4,
    float4* __restrict__ out4)
{
    const long long OFFK4 = N0_4 + NQ_4;
    const long long OFFV4 = OFFK4 + NK_4;
    long long base = c * CHUNK4 + tid;

    if (base < N0_4) {
        float4 a0 = inputs4[base];
        float4 a1 = inputs4[base + 256];
        out4[base]       = a0;
        out4[base + 256] = a1;
    } else if (base < N0_4 + NQ_4) {
        long long e = base - N0_4;
        float4 a0 = q4[e];
        float4 a1 = q4[e + 256];
        out4[base]       = a0;
        out4[base + 256] = a1;
    } else if (base < N0_4 + NQ_4 + NB_4) {
        long long e = base - (N0_4 + NQ_4);
        float4 a0 = k4[e];
        float4 a1 = k4[e + 256];
        // dst = OFFK4 + (bh*TT + KK + t)*16 + d4 = OFFK4 + e + 160*(bh+1)
        long long dst = OFFK4 + e + 160*((e >> 15) + 1);
        out4[dst]       = a0;
        out4[dst + 256] = a1;
    } else {
        long long e = base - (N0_4 + NQ_4 + NB_4);
        float4 a0 = v4[e];
        float4 a1 = v4[e + 256];
        long long dst = OFFV4 + e + 160*((e >> 15) + 1);
        out4[dst]       = a0;
        out4[dst + 256] = a1;
    }
}

// ---------------------------------------------------------------------------
// K1: blocks 0..499  -> sims (one warp per (b,m))
//     blocks 500..   -> copy chunks [0, K1_CHUNKS)
// ---------------------------------------------------------------------------
__global__ void __launch_bounds__(256) k1_sims_copy(
    const float4* __restrict__ inputs4, const float4* __restrict__ q4,
    const float4* __restrict__ k4, const float4* __restrict__ v4,
    const float4* __restrict__ mk4,
    float4* __restrict__ out4)
{
    int tid = threadIdx.x;

    if (blockIdx.x >= SIMS_BLOCKS) {
        copy_chunk(blockIdx.x - SIMS_BLOCKS, tid, inputs4, q4, k4, v4, out4);
        return;
    }

    // sims: one warp per (b,m)
    int wid = tid >> 5, lane = tid & 31;
    int wb = blockIdx.x * 8 + wid;            // 0..3999
    int b = wb / MM, m = wb % MM;

    const float4* row = mk4 + (size_t)m * HID4;
    // query_key[b][i] = k[b, i/64, S-1, i%64]; float4 chunks never cross h
    const float4* kb = k4 + (((long long)b*HH)*SS + (SS-1))*16;

    float dot = 0.f, sq = 0.f;
    #pragma unroll
    for (int j = 0; j < 8; j++) {
        int i4 = lane + 32*j;                 // 0..255
        float4 r  = row[i4];
        float4 qv = kb[(long long)(i4 >> 4)*SS*16 + (i4 & 15)];
        dot += qv.x*r.x + qv.y*r.y + qv.z*r.z + qv.w*r.w;
        sq  += r.x*r.x + r.y*r.y + r.z*r.z + r.w*r.w;
    }
    #pragma unroll
    for (int off = 16; off; off >>= 1) {
        dot += __shfl_down_sync(0xffffffffu, dot, off);
        sq  += __shfl_down_sync(0xffffffffu, sq,  off);
    }
    if (lane == 0)
        g_sims[wb] = dot / (sqrtf(sq) + EPSV);
}

// ---------------------------------------------------------------------------
// K2: blocks 0..3 -> retrieval (top-10, gather, mask, positions, scalar)
//     blocks 4..  -> copy chunks [K1_CHUNKS, TOT_CHUNKS)
// ---------------------------------------------------------------------------
__global__ void __launch_bounds__(256) k2_ret_copy(
    const float4* __restrict__ inputs4, const float4* __restrict__ q4,
    const float4* __restrict__ k4, const float4* __restrict__ v4,
    const float4* __restrict__ mk4, const float4* __restrict__ mv4,
    const float*  __restrict__ attn_mask,
    const float*  __restrict__ mem_pos,
    float4* __restrict__ out4,
    float*  __restrict__ out,
    long long off_mask, long long off_pos,
    long long off_seq, int has_scalar)
{
    int tid = threadIdx.x;

    if (blockIdx.x >= BB) {
        copy_chunk((long long)K1_CHUNKS + (blockIdx.x - BB), tid,
                   inputs4, q4, k4, v4, out4);
        return;
    }

    const long long OFFK4 = N0_4 + NQ_4;
    const long long OFFV4 = OFFK4 + NK_4;
    int b = blockIdx.x;

    __shared__ float ss[MM];
    __shared__ float rv[256];
    __shared__ int   ri[256];
    __shared__ int   top[KK];

    for (int i = tid; i < MM; i += 256)
        ss[i] = g_sims[b*MM + i];
    __syncthreads();

    // top-10: descending, lowest index on ties
    for (int j = 0; j < KK; j++) {
        float bv = -INFINITY; int bi = MM;
        for (int m = tid; m < MM; m += 256) {
            float vv = ss[m];
            if (vv > bv) { bv = vv; bi = m; }   // strict > => lowest idx wins
        }
        rv[tid] = bv; ri[tid] = bi;
        __syncthreads();
        for (int off = 128; off; off >>= 1) {
            if (tid < off) {
                float ov = rv[tid + off]; int oi = ri[tid + off];
                if (ov > rv[tid] || (ov == rv[tid] && oi < ri[tid])) {
                    rv[tid] = ov; ri[tid] = oi;
                }
            }
            __syncthreads();
        }
        if (tid == 0) { top[j] = ri[0]; ss[ri[0]] = -INFINITY; }
        __syncthreads();
    }

    // gather retrieved rows t<K of k_aug / v_aug (5120 float4)
    for (int e = tid; e < 2*KK*HID4; e += 256) {
        int which = e >= KK*HID4;
        int e2 = which ? e - KK*HID4 : e;
        int t  = e2 >> 8;
        int i4 = e2 & 255;
        int idx = top[t];
        float4 val = (which ? mv4 : mk4)[(size_t)idx*HID4 + i4];
        long long dst = (which ? OFFV4 : OFFK4)
                      + (((long long)b*HH + (i4 >> 4))*TT + t)*16 + (i4 & 15);
        out4[dst] = val;
    }

    // mask_aug[b] = [ones(K), attention_mask[b]]
    for (int t = tid; t < TT; t += 256)
        out[off_mask + (size_t)b*TT + t] =
            (t < KK) ? 1.0f : attn_mask[(size_t)b*SS + (t - KK)];

    // positions_k[b] = [arange(S), mem_positions[top_idx[b]]]
    for (int t = tid; t < TT; t += 256)
        out[off_pos + (size_t)b*TT + t] =
            (t < SS) ? (float)t : mem_pos[top[t - SS]];

    if (b == 0 && tid == 0 && has_scalar)
        out[off_seq] = (float)TT;
}

// ---------------------------------------------------------------------------
extern "C" void kernel_launch(void* const* d_in, const int* in_sizes, int n_in,
                              void* d_out, int out_size)
{
    const float* inputs = (const float*)d_in[0];
    const float* q      = (const float*)d_in[1];
    const float* k      = (const float*)d_in[2];
    const float* v      = (const float*)d_in[3];
    const float* mask   = (const float*)d_in[4];
    const float* mk     = (const float*)d_in[5];
    const float* mv     = (const float*)d_in[6];
    const float* mpos   = (const float*)d_in[7];
    float* out = (float*)d_out;

    const long long N0 = 4 * N0_4;
    const long long NQ = 4 * NQ_4;
    const long long NK = 4 * NK_4;

    const long long off_mask = N0 + NQ + 2*NK;
    const long long off_tail = off_mask + (long long)BB * TT;
    // tuple order: inputs, q, k_aug, v_aug, mask_aug, seq_len_k, positions_k
    const long long with_scalar = off_tail + 1 + (long long)BB * TT;
    int has_scalar = ((long long)out_size == with_scalar) ? 1 : 0;
    const long long off_seq = off_tail;
    const long long off_pos = off_tail + (has_scalar ? 1 : 0);

    // K1: sims + 25% of copy (sims hidden under copy)
    k1_sims_copy<<<SIMS_BLOCKS + K1_CHUNKS, 256>>>(
        (const float4*)inputs, (const float4*)q,
        (const float4*)k, (const float4*)v,
        (const float4*)mk, (float4*)out);

    // K2: retrieval + 75% of copy (retrieval hidden under copy)
    k2_ret_copy<<<BB + K2_CHUNKS, 256>>>(
        (const float4*)inputs, (const float4*)q,
        (const float4*)k, (const float4*)v,
        (const float4*)mk, (const float4*)mv,
        mask, mpos,
        (float4*)out, out,
        off_mask, off_pos, off_seq, has_scalar);
}

// round 8
// speedup vs baseline: 10.0359x; 1.1195x over previous
#include <cuda_runtime.h>
#include <math.h>

// Fixed shapes for EpisodicMemory_57810259804539
#define BB 4
#define HH 16
#define SS 2048
#define DD 64
#define MM 1000
#define KK 10
#define HID (HH*DD)       // 1024
#define TT (SS+KK)        // 2058
#define EPSV 1e-8f

#define N0_4  (BB*SS*HID/4)          // 2,097,152  inputs as float4
#define NQ_4  N0_4                    // q as float4
#define NK_4  (BB*HH*TT*DD/4)         // 2,107,392  k_aug/v_aug as float4
#define HID4  (HID/4)                 // 256 float4 per memory row

#define SIMS_BLOCKS 500               // 8 warps each -> 4000 (b,m)
#define OUT4_TOTAL  (N0_4 + NQ_4 + 2*NK_4)          // 8,409,088
#define COPY_BLOCKS ((OUT4_TOTAL + 255) / 256)      // 32,848

// Scratch
__device__ float g_sims[BB*MM];

// ---------------------------------------------------------------------------
// K1: sims only. One warp per (b,m). Triggers PDL completion immediately so
// K2's copy blocks launch underneath.
// ---------------------------------------------------------------------------
__global__ void __launch_bounds__(256) k1_sims(
    const float4* __restrict__ k4,
    const float4* __restrict__ mk4)
{
#if __CUDA_ARCH__ >= 900
    cudaTriggerProgrammaticLaunchCompletion();
#endif
    int tid = threadIdx.x;
    int wid = tid >> 5, lane = tid & 31;
    int wb = blockIdx.x * 8 + wid;            // 0..3999
    int b = wb / MM, m = wb % MM;

    const float4* row = mk4 + (size_t)m * HID4;
    // query_key[b][i] = k[b, i/64, S-1, i%64]; float4 chunks never cross h
    const float4* kb = k4 + ((b*HH)*SS + (SS-1))*16;

    float dot = 0.f, sq = 0.f;
    #pragma unroll
    for (int j = 0; j < 8; j++) {
        int i4 = lane + 32*j;                 // 0..255
        float4 r  = row[i4];
        float4 qv = kb[(i4 >> 4)*SS*16 + (i4 & 15)];
        dot += qv.x*r.x + qv.y*r.y + qv.z*r.z + qv.w*r.w;
        sq  += r.x*r.x + r.y*r.y + r.z*r.z + r.w*r.w;
    }
    #pragma unroll
    for (int off = 16; off; off >>= 1) {
        dot += __shfl_down_sync(0xffffffffu, dot, off);
        sq  += __shfl_down_sync(0xffffffffu, sq,  off);
    }
    if (lane == 0)
        g_sims[wb] = dot / (sqrtf(sq) + EPSV);
}

// ---------------------------------------------------------------------------
// K2: blocks 0..3  -> retrieval: PDL-wait on K1, top-10, gather t<K rows,
//                    mask_aug, positions_k, scalar.
//     blocks 4..   -> output-major copy, 1 float4/thread (R2-proven shape).
//                    t<K rows of k_aug/v_aug are skipped (retrieval owns them)
//                    so copy blocks never depend on K1.
// ---------------------------------------------------------------------------
__global__ void __launch_bounds__(256) k2_main(
    const float4* __restrict__ inputs4, const float4* __restrict__ q4,
    const float4* __restrict__ k4, const float4* __restrict__ v4,
    const float4* __restrict__ mk4, const float4* __restrict__ mv4,
    const float*  __restrict__ attn_mask,
    const float*  __restrict__ mem_pos,
    float4* __restrict__ out4,
    float*  __restrict__ out,
    int off_mask, int off_pos, int off_seq, int has_scalar)
{
    const int OFFK4 = N0_4 + NQ_4;            // k_aug start (float4)
    const int OFFV4 = OFFK4 + NK_4;           // v_aug start
    int tid = threadIdx.x;

    if (blockIdx.x >= BB) {
        // ---------------- copy blocks: enumerate OUTPUT index ------------
        int e = (int)(blockIdx.x - BB) * 256 + tid;
        if (e < N0_4) { out4[e] = inputs4[e]; return; }
        if (e < N0_4 + NQ_4) { out4[e] = q4[e - N0_4]; return; }
        int e2 = e - (N0_4 + NQ_4);
        if (e2 >= 2*NK_4) return;
        int which = e2 >= NK_4;
        int e3 = which ? e2 - NK_4 : e2;
        int d4 = e3 & 15;
        int r  = e3 >> 4;                     // bh*TT + t
        int t  = r % TT;
        int bh = r / TT;
        if (t < KK) return;                   // retrieval blocks own these
        const float4* s = which ? v4 : k4;
        out4[e] = s[(bh*SS + (t - KK))*16 + d4];
        return;
    }

    // ---------------- retrieval block for batch b ------------------------
#if __CUDA_ARCH__ >= 900
    cudaGridDependencySynchronize();          // wait for K1's g_sims
#endif
    int b = blockIdx.x;

    __shared__ float ss[MM];
    __shared__ float rv[256];
    __shared__ int   ri[256];
    __shared__ int   top[KK];

    for (int i = tid; i < MM; i += 256)
        ss[i] = g_sims[b*MM + i];
    __syncthreads();

    // top-10: descending, lowest index on ties
    for (int j = 0; j < KK; j++) {
        float bv = -INFINITY; int bi = MM;
        for (int m = tid; m < MM; m += 256) {
            float vv = ss[m];
            if (vv > bv) { bv = vv; bi = m; }   // strict > => lowest idx wins
        }
        rv[tid] = bv; ri[tid] = bi;
        __syncthreads();
        for (int off = 128; off; off >>= 1) {
            if (tid < off) {
                float ov = rv[tid + off]; int oi = ri[tid + off];
                if (ov > rv[tid] || (ov == rv[tid] && oi < ri[tid])) {
                    rv[tid] = ov; ri[tid] = oi;
                }
            }
            __syncthreads();
        }
        if (tid == 0) { top[j] = ri[0]; ss[ri[0]] = -INFINITY; }
        __syncthreads();
    }

    // gather retrieved rows t<K of k_aug / v_aug (5120 float4)
    for (int e = tid; e < 2*KK*HID4; e += 256) {
        int which = e >= KK*HID4;
        int e2 = which ? e - KK*HID4 : e;
        int t  = e2 >> 8;
        int i4 = e2 & 255;
        int idx = top[t];
        float4 val = (which ? mv4 : mk4)[(size_t)idx*HID4 + i4];
        int dst = (which ? OFFV4 : OFFK4)
                + ((b*HH + (i4 >> 4))*TT + t)*16 + (i4 & 15);
        out4[dst] = val;
    }

    // mask_aug[b] = [ones(K), attention_mask[b]]
    for (int t = tid; t < TT; t += 256)
        out[off_mask + b*TT + t] =
            (t < KK) ? 1.0f : attn_mask[b*SS + (t - KK)];

    // positions_k[b] = [arange(S), mem_positions[top_idx[b]]]
    for (int t = tid; t < TT; t += 256)
        out[off_pos + b*TT + t] =
            (t < SS) ? (float)t : mem_pos[top[t - SS]];

    if (b == 0 && tid == 0 && has_scalar)
        out[off_seq] = (float)TT;
}

// ---------------------------------------------------------------------------
extern "C" void kernel_launch(void* const* d_in, const int* in_sizes, int n_in,
                              void* d_out, int out_size)
{
    const float* inputs = (const float*)d_in[0];
    const float* q      = (const float*)d_in[1];
    const float* k      = (const float*)d_in[2];
    const float* v      = (const float*)d_in[3];
    const float* mask   = (const float*)d_in[4];
    const float* mk     = (const float*)d_in[5];
    const float* mv     = (const float*)d_in[6];
    const float* mpos   = (const float*)d_in[7];
    float* out = (float*)d_out;

    const int off_mask = OUT4_TOTAL * 4;                 // after the 4 big tensors
    const int off_tail = off_mask + BB * TT;
    // tuple order: inputs, q, k_aug, v_aug, mask_aug, seq_len_k, positions_k
    const int with_scalar = off_tail + 1 + BB * TT;
    int has_scalar = (out_size == with_scalar) ? 1 : 0;
    const int off_seq = off_tail;
    const int off_pos = off_tail + (has_scalar ? 1 : 0);

    // K1: sims (triggers PDL completion at entry)
    k1_sims<<<SIMS_BLOCKS, 256>>>((const float4*)k, (const float4*)mk);

    // K2: retrieval + copy, launched with programmatic stream serialization
    // so copy blocks overlap K1; only retrieval blocks grid-dep-sync.
    {
        cudaLaunchConfig_t cfg = {};
        cfg.gridDim  = dim3(BB + COPY_BLOCKS, 1, 1);
        cfg.blockDim = dim3(256, 1, 1);
        cfg.dynamicSmemBytes = 0;
        cfg.stream = 0;
        cudaLaunchAttribute attrs[1];
        attrs[0].id = cudaLaunchAttributeProgrammaticStreamSerialization;
        attrs[0].val.programmaticStreamSerializationAllowed = 1;
        cfg.attrs = attrs;
        cfg.numAttrs = 1;
        cudaLaunchKernelEx(&cfg, k2_main,
            (const float4*)inputs, (const float4*)q,
            (const float4*)k, (const float4*)v,
            (const float4*)mk, (const float4*)mv,
            mask, mpos,
            (float4*)out, out,
            off_mask, off_pos, off_seq, has_scalar);
    }
}